// round 12
// baseline (speedup 1.0000x reference)
#include <cuda_runtime.h>
#include <cuda_fp16.h>

#define Nn 100000
#define Ff 64
#define Ee 1600000
#define H0CNT 50048          // chunk 0 node count (= 391*128)

typedef unsigned long long ull;

// Scratch (device globals — no allocation allowed anywhere)
__device__ float  g_deg[Nn];
__device__ float  g_dinv[Nn];
__device__ int    g_cnt[Nn];
__device__ int    g_off[Nn];
__device__ int    g_ctr;              // global CSR cursor
__device__ int    g_rank[Ee];         // per-edge rank within its column
__device__ int2   g_csr[Ee];          // (row, __float_as_int(nw))
__device__ float  g_h0[(size_t)Nn * Ff];
__device__ float  g_out1[(size_t)Nn * Ff];
__device__ __half g_h16[(size_t)Nn * Ff];    // fp16 shadow of h0   (gather src)
__device__ __half g_o16[(size_t)Nn * Ff];    // fp16 shadow of out1 (gather src)
__device__ __half g_agg16[(size_t)Nn * Ff];  // fp16 aggregate

// ---- packed f32x2 helpers (sm_103a FFMA2 — only reachable via PTX) --------
__device__ __forceinline__ ull fma2(ull a, ull b, ull c) {
    ull d;
    asm("fma.rn.f32x2 %0, %1, %2, %3;" : "=l"(d) : "l"(a), "l"(b), "l"(c));
    return d;
}
__device__ __forceinline__ ull dup2(float x) {
    ull d;
    asm("mov.b64 %0, {%1, %1};" : "=l"(d) : "f"(x));
    return d;
}
__device__ __forceinline__ void unpack2(ull v, float& lo, float& hi) {
    asm("mov.b64 {%0, %1}, %2;" : "=f"(lo), "=f"(hi) : "l"(v));
}

// ---------------------------------------------------------------------------
__global__ void zero_kernel() {
    int i = blockIdx.x * blockDim.x + threadIdx.x;
    if (i < Nn) { g_deg[i] = 0.f; g_cnt[i] = 0; }
    if (i == 0) g_ctr = 0;
}

// ---------------------------------------------------------------------------
// deg[col[e]] += w[e];  rank[e] = cnt[col[e]]++   (2 edges per thread)
// ---------------------------------------------------------------------------
__global__ void deg_kernel(const int* __restrict__ cols,
                           const float* __restrict__ ew) {
    int e2 = blockIdx.x * blockDim.x + threadIdx.x;   // edge-pair index
    if (e2 * 2 + 1 < Ee) {
        int2 c = *(const int2*)(cols + e2 * 2);
        float2 w = *(const float2*)(ew + e2 * 2);
        int r0 = 0, r1 = 0;
        if ((unsigned)c.x < Nn) {
            atomicAdd(&g_deg[c.x], w.x);
            r0 = atomicAdd(&g_cnt[c.x], 1);
        }
        if ((unsigned)c.y < Nn) {
            atomicAdd(&g_deg[c.y], w.y);
            r1 = atomicAdd(&g_cnt[c.y], 1);
        }
        *(int2*)(g_rank + e2 * 2) = make_int2(r0, r1);
    } else if (e2 * 2 < Ee) {
        int c = cols[e2 * 2];
        if ((unsigned)c < Nn) {
            atomicAdd(&g_deg[c], ew[e2 * 2]);
            g_rank[e2 * 2] = atomicAdd(&g_cnt[c], 1);
        }
    }
}

// ---------------------------------------------------------------------------
// One-kernel CSR slot allocator (replaces 3-phase scan): warp-inclusive scan
// of cnt + one global atomicAdd per warp. Ranges are disjoint (order-free).
// Also computes dinv.
// ---------------------------------------------------------------------------
__global__ void alloc_kernel() {
    int i = blockIdx.x * blockDim.x + threadIdx.x;
    int lane = threadIdx.x & 31;
    int v = (i < Nn) ? g_cnt[i] : 0;
    int incl = v;
#pragma unroll
    for (int d = 1; d < 32; d <<= 1) {
        int u = __shfl_up_sync(0xffffffffu, incl, d);
        if (lane >= d) incl += u;
    }
    int total = __shfl_sync(0xffffffffu, incl, 31);
    int base = 0;
    if (lane == 31 && total > 0) base = atomicAdd(&g_ctr, total);
    base = __shfl_sync(0xffffffffu, base, 31);
    if (i < Nn) {
        g_off[i] = base + incl - v;
        float dg = g_deg[i];
        g_dinv[i] = dg > 0.f ? rsqrtf(dg) : 0.f;
    }
}

// ---------------------------------------------------------------------------
// Scatter edges into packed CSR slots — NO atomics (rank precomputed).
// ---------------------------------------------------------------------------
__global__ void scatter_kernel(const int* __restrict__ rows,
                               const int* __restrict__ cols,
                               const float* __restrict__ ew) {
    int e2 = blockIdx.x * blockDim.x + threadIdx.x;
    if (e2 * 2 + 1 < Ee) {
        int2 r = *(const int2*)(rows + e2 * 2);
        int2 c = *(const int2*)(cols + e2 * 2);
        float2 w = *(const float2*)(ew + e2 * 2);
        int2 rk = *(const int2*)(g_rank + e2 * 2);
        if ((unsigned)r.x < Nn && (unsigned)c.x < Nn) {
            int p = g_off[c.x] + rk.x;
            g_csr[p] = make_int2(r.x, __float_as_int(g_dinv[r.x] * w.x * g_dinv[c.x]));
        }
        if ((unsigned)r.y < Nn && (unsigned)c.y < Nn) {
            int p = g_off[c.y] + rk.y;
            g_csr[p] = make_int2(r.y, __float_as_int(g_dinv[r.y] * w.y * g_dinv[c.y]));
        }
    } else if (e2 * 2 < Ee) {
        int r = rows[e2 * 2], c = cols[e2 * 2];
        if ((unsigned)r < Nn && (unsigned)c < Nn) {
            int p = g_off[c] + g_rank[e2 * 2];
            g_csr[p] = make_int2(r, __float_as_int(g_dinv[r] * ew[e2 * 2] * g_dinv[c]));
        }
    }
}

// ---------------------------------------------------------------------------
// SpMM gather (fp16 src, fp16 dst) over node range [nbase, nbase+ncnt):
// agg16[n] = sum nw * h16[row]. One warp per node, lane owns 2 feats.
// ---------------------------------------------------------------------------
__global__ void __launch_bounds__(256)
gather_kernel(int src, int nbase, int ncnt) {
    int w = nbase + ((blockIdx.x * 256 + threadIdx.x) >> 5);
    int lane = threadIdx.x & 31;
    if (w >= nbase + ncnt || w >= Nn) return;
    const __half* __restrict__ h = src ? g_o16 : g_h16;
    int beg = g_off[w];
    int end = beg + g_cnt[w];
    float2 a0 = make_float2(0.f, 0.f);
    float2 a1 = make_float2(0.f, 0.f);
    float2 a2 = make_float2(0.f, 0.f);
    float2 a3 = make_float2(0.f, 0.f);
    int j = beg;
    for (; j + 4 <= end; j += 4) {
        int2 c0 = g_csr[j];
        int2 c1 = g_csr[j + 1];
        int2 c2 = g_csr[j + 2];
        int2 c3 = g_csr[j + 3];
        float2 v0 = __half22float2(*(const __half2*)(h + (size_t)c0.x * Ff + lane * 2));
        float2 v1 = __half22float2(*(const __half2*)(h + (size_t)c1.x * Ff + lane * 2));
        float2 v2 = __half22float2(*(const __half2*)(h + (size_t)c2.x * Ff + lane * 2));
        float2 v3 = __half22float2(*(const __half2*)(h + (size_t)c3.x * Ff + lane * 2));
        float w0 = __int_as_float(c0.y), w1 = __int_as_float(c1.y);
        float w2 = __int_as_float(c2.y), w3 = __int_as_float(c3.y);
        a0.x = fmaf(w0, v0.x, a0.x); a0.y = fmaf(w0, v0.y, a0.y);
        a1.x = fmaf(w1, v1.x, a1.x); a1.y = fmaf(w1, v1.y, a1.y);
        a2.x = fmaf(w2, v2.x, a2.x); a2.y = fmaf(w2, v2.y, a2.y);
        a3.x = fmaf(w3, v3.x, a3.x); a3.y = fmaf(w3, v3.y, a3.y);
    }
    for (; j < end; j++) {
        int2 c0 = g_csr[j];
        float2 v0 = __half22float2(*(const __half2*)(h + (size_t)c0.x * Ff + lane * 2));
        float w0 = __int_as_float(c0.y);
        a0.x = fmaf(w0, v0.x, a0.x); a0.y = fmaf(w0, v0.y, a0.y);
    }
    a0.x += a1.x + a2.x + a3.x;
    a0.y += a1.y + a2.y + a3.y;
    *(__half2*)(g_agg16 + (size_t)w * Ff + lane * 2) = __floats2half2_rn(a0.x, a0.y);
}

// ---------------------------------------------------------------------------
// GEMM h0 = relu(x @ W0^T + b).  Also writes fp16 shadow for the gather.
// ---------------------------------------------------------------------------
__global__ void __launch_bounds__(256)
gemm_h0_kernel(const float* __restrict__ x, const float* __restrict__ w0,
               const float* __restrict__ b) {
    __shared__ __align__(16) float As[64][128];  // [k][node]
    __shared__ __align__(16) float Ws[64][64];   // [k][f]
    int t = threadIdx.x;
    int n0 = blockIdx.x * 128;

    for (int i = t; i < 4096; i += 256) {
        int k = i >> 6, f = i & 63;
        Ws[k][f] = w0[f * 64 + k];  // transpose: need W0[f][k] at [k][f]
    }
    for (int i = t * 4; i < 8192; i += 1024) {
        int node = i >> 6, k = i & 63;
        int gn = n0 + node;
        float4 v = make_float4(0.f, 0.f, 0.f, 0.f);
        if (gn < Nn) v = *(const float4*)(x + (size_t)gn * 64 + k);
        As[k + 0][node] = v.x; As[k + 1][node] = v.y;
        As[k + 2][node] = v.z; As[k + 3][node] = v.w;
    }
    __syncthreads();

    int tf = (t & 15) * 4;
    int tn = (t >> 4) * 8;
    float acc[8][4];
#pragma unroll
    for (int j = 0; j < 8; j++)
        acc[j][0] = acc[j][1] = acc[j][2] = acc[j][3] = 0.f;

#pragma unroll 8
    for (int k = 0; k < 64; k++) {
        float4 w4 = *(const float4*)&Ws[k][tf];
        float4 b0v = *(const float4*)&As[k][tn];
        float4 b1v = *(const float4*)&As[k][tn + 4];
        float a[8] = {b0v.x, b0v.y, b0v.z, b0v.w, b1v.x, b1v.y, b1v.z, b1v.w};
#pragma unroll
        for (int j = 0; j < 8; j++) {
            acc[j][0] = fmaf(a[j], w4.x, acc[j][0]);
            acc[j][1] = fmaf(a[j], w4.y, acc[j][1]);
            acc[j][2] = fmaf(a[j], w4.z, acc[j][2]);
            acc[j][3] = fmaf(a[j], w4.w, acc[j][3]);
        }
    }
    float4 bv = *(const float4*)(b + tf);
#pragma unroll
    for (int j = 0; j < 8; j++) {
        int gn = n0 + tn + j;
        if (gn < Nn) {
            float4 r;
            r.x = fmaxf(acc[j][0] + bv.x, 0.f);
            r.y = fmaxf(acc[j][1] + bv.y, 0.f);
            r.z = fmaxf(acc[j][2] + bv.z, 0.f);
            r.w = fmaxf(acc[j][3] + bv.w, 0.f);
            *(float4*)&g_h0[(size_t)gn * 64 + tf] = r;
            __half2 p0 = __floats2half2_rn(r.x, r.y);
            __half2 p1 = __floats2half2_rn(r.z, r.w);
            *(__half2*)&g_h16[(size_t)gn * 64 + tf] = p0;
            *(__half2*)&g_h16[(size_t)gn * 64 + tf + 2] = p1;
        }
    }
}

// ---------------------------------------------------------------------------
// Fused conv GEMM over node range starting at nbase (grid sized per chunk):
//   out = prev + relu( (0.1*agg16 + 0.9*h0) @ W1 )   — f32x2 FFMA2 main loop
// ---------------------------------------------------------------------------
__global__ void __launch_bounds__(256)
gemm_conv_kernel(const float* __restrict__ w1, int layer,
                 float* __restrict__ dout, int nbase) {
    __shared__ __align__(16) float As[64][128];
    __shared__ __align__(16) float Ws[64][64];
    int t = threadIdx.x;
    int n0 = nbase + blockIdx.x * 128;
    const float* __restrict__ prev = layer ? g_out1 : g_h0;
    float* __restrict__ out = layer ? dout : g_out1;

    for (int i = t; i < 4096; i += 256) {
        Ws[i >> 6][i & 63] = w1[i];  // already [k][f]
    }
    for (int i = t * 4; i < 8192; i += 1024) {
        int node = i >> 6, k = i & 63;
        int gn = n0 + node;
        float4 v = make_float4(0.f, 0.f, 0.f, 0.f);
        if (gn < Nn) {
            float2 alo = __half22float2(*(const __half2*)(g_agg16 + (size_t)gn * 64 + k));
            float2 ahi = __half22float2(*(const __half2*)(g_agg16 + (size_t)gn * 64 + k + 2));
            float4 h = *(const float4*)(g_h0 + (size_t)gn * 64 + k);
            v.x = fmaf(0.1f, alo.x, 0.9f * h.x);
            v.y = fmaf(0.1f, alo.y, 0.9f * h.y);
            v.z = fmaf(0.1f, ahi.x, 0.9f * h.z);
            v.w = fmaf(0.1f, ahi.y, 0.9f * h.w);
        }
        As[k + 0][node] = v.x; As[k + 1][node] = v.y;
        As[k + 2][node] = v.z; As[k + 3][node] = v.w;
    }
    __syncthreads();

    int tf = (t & 15) * 4;
    int tn = (t >> 4) * 8;

    ull acc2[4][4];
#pragma unroll
    for (int jp = 0; jp < 4; jp++)
#pragma unroll
        for (int c = 0; c < 4; c++) acc2[jp][c] = 0ull;

#pragma unroll 8
    for (int k = 0; k < 64; k++) {
        float4 w4 = *(const float4*)&Ws[k][tf];
        ull wd0 = dup2(w4.x), wd1 = dup2(w4.y), wd2 = dup2(w4.z), wd3 = dup2(w4.w);
        ulonglong2 ap0 = *(const ulonglong2*)&As[k][tn];
        ulonglong2 ap1 = *(const ulonglong2*)&As[k][tn + 4];
        ull ap[4] = {ap0.x, ap0.y, ap1.x, ap1.y};
#pragma unroll
        for (int jp = 0; jp < 4; jp++) {
            acc2[jp][0] = fma2(ap[jp], wd0, acc2[jp][0]);
            acc2[jp][1] = fma2(ap[jp], wd1, acc2[jp][1]);
            acc2[jp][2] = fma2(ap[jp], wd2, acc2[jp][2]);
            acc2[jp][3] = fma2(ap[jp], wd3, acc2[jp][3]);
        }
    }

    float acc[8][4];
#pragma unroll
    for (int jp = 0; jp < 4; jp++)
#pragma unroll
        for (int c = 0; c < 4; c++)
            unpack2(acc2[jp][c], acc[2 * jp][c], acc[2 * jp + 1][c]);

#pragma unroll
    for (int j = 0; j < 8; j++) {
        int gn = n0 + tn + j;
        if (gn < Nn) {
            float4 p = *(const float4*)(prev + (size_t)gn * 64 + tf);
            float4 r;
            r.x = p.x + fmaxf(acc[j][0], 0.f);
            r.y = p.y + fmaxf(acc[j][1], 0.f);
            r.z = p.z + fmaxf(acc[j][2], 0.f);
            r.w = p.w + fmaxf(acc[j][3], 0.f);
            *(float4*)(out + (size_t)gn * 64 + tf) = r;
            if (layer == 0) {
                __half2 p0 = __floats2half2_rn(r.x, r.y);
                __half2 p1 = __floats2half2_rn(r.z, r.w);
                *(__half2*)&g_o16[(size_t)gn * 64 + tf] = p0;
                *(__half2*)&g_o16[(size_t)gn * 64 + tf + 2] = p1;
            }
        }
    }
}

// ---------------------------------------------------------------------------
extern "C" void kernel_launch(void* const* d_in, const int* in_sizes, int n_in,
                              void* d_out, int out_size) {
    const float* x  = (const float*)d_in[0];
    const int*   ei = (const int*)d_in[1];   // int32 (harness: int64 -> int32)
    const float* ew = (const float*)d_in[2];
    // d_in[3] = edge_attr (unused by the module)
    const float* w0 = (const float*)d_in[4];
    const float* b0 = (const float*)d_in[5];
    const float* w1 = (const float*)d_in[6];
    float* out = (float*)d_out;

    const int* rows = ei;
    const int* cols = ei + Ee;

    const int E2B = (Ee / 2 + 255) / 256;   // 2 edges per thread
    const int NB = (Nn + 255) / 256;
    const int GB = (Nn + 127) / 128;        // full gemm grid (h0)
    const int H1CNT = Nn - H0CNT;           // 49952
    const int GB0 = H0CNT / 128;            // 391
    const int GB1 = (H1CNT + 127) / 128;    // 391
    const int WB0 = (H0CNT + 7) / 8;
    const int WB1 = (H1CNT + 7) / 8;

    static cudaStream_t s1 = nullptr;
    static cudaEvent_t ev[8];  // 0:fork 1:h0 2:eg0 3:eg1 4:ec1 5:eg2 6:eg3 7:ec3
    if (s1 == nullptr) {
        cudaStreamCreateWithFlags(&s1, cudaStreamNonBlocking);
        for (int i = 0; i < 8; i++)
            cudaEventCreateWithFlags(&ev[i], cudaEventDisableTiming);
    }

    // Fork: gemm_h0 on s1 (independent of the CSR build chain).
    cudaEventRecord(ev[0], 0);
    cudaStreamWaitEvent(s1, ev[0], 0);
    gemm_h0_kernel<<<GB, 256, 0, s1>>>(x, w0, b0);
    cudaEventRecord(ev[1], s1);

    // CSR build chain on stream 0.
    zero_kernel<<<NB, 256>>>();
    deg_kernel<<<E2B, 256>>>(cols, ew);
    alloc_kernel<<<NB, 256>>>();             // scan + dinv in one kernel
    scatter_kernel<<<E2B, 256>>>(rows, cols, ew);
    cudaStreamWaitEvent(0, ev[1], 0);        // gathers need h16

    // ---- layer 0: gathers paced on stream 0, convs chase on s1 ----
    gather_kernel<<<WB0, 256>>>(0, 0, H0CNT);
    cudaEventRecord(ev[2], 0);
    gather_kernel<<<WB1, 256>>>(0, H0CNT, H1CNT);
    cudaEventRecord(ev[3], 0);
    cudaStreamWaitEvent(s1, ev[2], 0);
    gemm_conv_kernel<<<GB0, 256, 0, s1>>>(w1, 0, out, 0);
    cudaStreamWaitEvent(s1, ev[3], 0);
    gemm_conv_kernel<<<GB1, 256, 0, s1>>>(w1, 0, out, H0CNT);
    cudaEventRecord(ev[4], s1);
    cudaStreamWaitEvent(0, ev[4], 0);        // layer barrier (gather1 needs all o16)

    // ---- layer 1 ----
    gather_kernel<<<WB0, 256>>>(1, 0, H0CNT);
    cudaEventRecord(ev[5], 0);
    gather_kernel<<<WB1, 256>>>(1, H0CNT, H1CNT);
    cudaEventRecord(ev[6], 0);
    cudaStreamWaitEvent(s1, ev[5], 0);
    gemm_conv_kernel<<<GB0, 256, 0, s1>>>(w1 + 64 * 64, 1, out, 0);
    cudaStreamWaitEvent(s1, ev[6], 0);
    gemm_conv_kernel<<<GB1, 256, 0, s1>>>(w1 + 64 * 64, 1, out, H0CNT);
    cudaEventRecord(ev[7], s1);
    cudaStreamWaitEvent(0, ev[7], 0);        // join s1 back before capture ends
}

// round 13
// speedup vs baseline: 1.0714x; 1.0714x over previous
#include <cuda_runtime.h>
#include <cuda_fp16.h>

#define Nn 100000
#define Ff 64
#define Ee 1600000

typedef unsigned long long ull;

#define FIXS 16777216.0f          // 2^24 fixed-point scale for deg
#define DEGMASK 0xFFFFFFFFFFULL   // low 40 bits

// Scratch (device globals — no allocation allowed anywhere)
__device__ ull    g_packed[Nn];       // [63:40]=cnt, [39:0]=deg in 2^-24 fixed
__device__ float  g_dinv[Nn];
__device__ int2   g_range[Nn];        // (beg, end) CSR slot range per node
__device__ int    g_ctr;              // global CSR cursor
__device__ int    g_rank[Ee];         // per-edge rank within its column
__device__ int2   g_csr[Ee];          // (row, __float_as_int(nw))
__device__ float  g_h0[(size_t)Nn * Ff];
__device__ float  g_out1[(size_t)Nn * Ff];
__device__ __half g_h16[(size_t)Nn * Ff];    // fp16 shadow of h0   (gather src)
__device__ __half g_o16[(size_t)Nn * Ff];    // fp16 shadow of out1 (gather src)
__device__ __half g_agg16[(size_t)Nn * Ff];  // fp16 aggregate

// ---- packed f32x2 helpers (sm_103a FFMA2 — only reachable via PTX) --------
__device__ __forceinline__ ull fma2(ull a, ull b, ull c) {
    ull d;
    asm("fma.rn.f32x2 %0, %1, %2, %3;" : "=l"(d) : "l"(a), "l"(b), "l"(c));
    return d;
}
__device__ __forceinline__ ull dup2(float x) {
    ull d;
    asm("mov.b64 %0, {%1, %1};" : "=l"(d) : "f"(x));
    return d;
}
__device__ __forceinline__ void unpack2(ull v, float& lo, float& hi) {
    asm("mov.b64 {%0, %1}, %2;" : "=f"(lo), "=f"(hi) : "l"(v));
}

// ---------------------------------------------------------------------------
__global__ void zero_kernel() {
    int i = blockIdx.x * blockDim.x + threadIdx.x;
    if (i < Nn) g_packed[i] = 0ull;
    if (i == 0) g_ctr = 0;
}

// ---------------------------------------------------------------------------
// ONE packed 64-bit atomic per edge: high 24 bits count, low 40 bits deg
// (2^-24 fixed point). Old value's high bits = this edge's rank in its column.
// ---------------------------------------------------------------------------
__global__ void deg_kernel(const int* __restrict__ cols,
                           const float* __restrict__ ew) {
    int e2 = blockIdx.x * blockDim.x + threadIdx.x;   // edge-pair index
    if (e2 * 2 + 1 < Ee) {
        int2 c = *(const int2*)(cols + e2 * 2);
        float2 w = *(const float2*)(ew + e2 * 2);
        int r0 = 0, r1 = 0;
        if ((unsigned)c.x < Nn) {
            ull inc = (1ULL << 40) + (ull)__float2uint_rn(w.x * FIXS);
            r0 = (int)(atomicAdd(&g_packed[c.x], inc) >> 40);
        }
        if ((unsigned)c.y < Nn) {
            ull inc = (1ULL << 40) + (ull)__float2uint_rn(w.y * FIXS);
            r1 = (int)(atomicAdd(&g_packed[c.y], inc) >> 40);
        }
        *(int2*)(g_rank + e2 * 2) = make_int2(r0, r1);
    } else if (e2 * 2 < Ee) {
        int c = cols[e2 * 2];
        if ((unsigned)c < Nn) {
            ull inc = (1ULL << 40) + (ull)__float2uint_rn(ew[e2 * 2] * FIXS);
            g_rank[e2 * 2] = (int)(atomicAdd(&g_packed[c], inc) >> 40);
        }
    }
}

// ---------------------------------------------------------------------------
// One-kernel CSR slot allocator: warp-inclusive scan of cnt + one global
// atomicAdd per warp (ranges disjoint, order-free). Also computes dinv.
// ---------------------------------------------------------------------------
__global__ void alloc_kernel() {
    int i = blockIdx.x * blockDim.x + threadIdx.x;
    int lane = threadIdx.x & 31;
    ull p = (i < Nn) ? g_packed[i] : 0ull;
    int v = (int)(p >> 40);
    int incl = v;
#pragma unroll
    for (int d = 1; d < 32; d <<= 1) {
        int u = __shfl_up_sync(0xffffffffu, incl, d);
        if (lane >= d) incl += u;
    }
    int total = __shfl_sync(0xffffffffu, incl, 31);
    int base = 0;
    if (lane == 31 && total > 0) base = atomicAdd(&g_ctr, total);
    base = __shfl_sync(0xffffffffu, base, 31);
    if (i < Nn) {
        int beg = base + incl - v;
        g_range[i] = make_int2(beg, beg + v);
        float dg = (float)(p & DEGMASK) * (1.0f / FIXS);
        g_dinv[i] = dg > 0.f ? rsqrtf(dg) : 0.f;
    }
}

// ---------------------------------------------------------------------------
// Scatter edges into packed CSR slots — NO atomics (rank precomputed).
// ---------------------------------------------------------------------------
__global__ void scatter_kernel(const int* __restrict__ rows,
                               const int* __restrict__ cols,
                               const float* __restrict__ ew) {
    int e2 = blockIdx.x * blockDim.x + threadIdx.x;
    if (e2 * 2 + 1 < Ee) {
        int2 r = *(const int2*)(rows + e2 * 2);
        int2 c = *(const int2*)(cols + e2 * 2);
        float2 w = *(const float2*)(ew + e2 * 2);
        int2 rk = *(const int2*)(g_rank + e2 * 2);
        if ((unsigned)r.x < Nn && (unsigned)c.x < Nn) {
            int p = g_range[c.x].x + rk.x;
            g_csr[p] = make_int2(r.x, __float_as_int(g_dinv[r.x] * w.x * g_dinv[c.x]));
        }
        if ((unsigned)r.y < Nn && (unsigned)c.y < Nn) {
            int p = g_range[c.y].x + rk.y;
            g_csr[p] = make_int2(r.y, __float_as_int(g_dinv[r.y] * w.y * g_dinv[c.y]));
        }
    } else if (e2 * 2 < Ee) {
        int r = rows[e2 * 2], c = cols[e2 * 2];
        if ((unsigned)r < Nn && (unsigned)c < Nn) {
            int p = g_range[c].x + g_rank[e2 * 2];
            g_csr[p] = make_int2(r, __float_as_int(g_dinv[r] * ew[e2 * 2] * g_dinv[c]));
        }
    }
}

// ---------------------------------------------------------------------------
// SpMM gather (fp16 src, fp16 dst): agg16[n] = sum nw * h16[row].
// One warp per node, lane owns 2 feats. 4 independent streams for MLP.
// ---------------------------------------------------------------------------
__global__ void __launch_bounds__(256)
gather_kernel(int src) {
    int w = (blockIdx.x * 256 + threadIdx.x) >> 5;   // node id
    int lane = threadIdx.x & 31;
    if (w >= Nn) return;
    const __half* __restrict__ h = src ? g_o16 : g_h16;
    int2 rg = g_range[w];
    int beg = rg.x, end = rg.y;
    float2 a0 = make_float2(0.f, 0.f);
    float2 a1 = make_float2(0.f, 0.f);
    float2 a2 = make_float2(0.f, 0.f);
    float2 a3 = make_float2(0.f, 0.f);
    int j = beg;
    for (; j + 4 <= end; j += 4) {
        int2 c0 = g_csr[j];
        int2 c1 = g_csr[j + 1];
        int2 c2 = g_csr[j + 2];
        int2 c3 = g_csr[j + 3];
        float2 v0 = __half22float2(*(const __half2*)(h + (size_t)c0.x * Ff + lane * 2));
        float2 v1 = __half22float2(*(const __half2*)(h + (size_t)c1.x * Ff + lane * 2));
        float2 v2 = __half22float2(*(const __half2*)(h + (size_t)c2.x * Ff + lane * 2));
        float2 v3 = __half22float2(*(const __half2*)(h + (size_t)c3.x * Ff + lane * 2));
        float w0 = __int_as_float(c0.y), w1 = __int_as_float(c1.y);
        float w2 = __int_as_float(c2.y), w3 = __int_as_float(c3.y);
        a0.x = fmaf(w0, v0.x, a0.x); a0.y = fmaf(w0, v0.y, a0.y);
        a1.x = fmaf(w1, v1.x, a1.x); a1.y = fmaf(w1, v1.y, a1.y);
        a2.x = fmaf(w2, v2.x, a2.x); a2.y = fmaf(w2, v2.y, a2.y);
        a3.x = fmaf(w3, v3.x, a3.x); a3.y = fmaf(w3, v3.y, a3.y);
    }
    for (; j < end; j++) {
        int2 c0 = g_csr[j];
        float2 v0 = __half22float2(*(const __half2*)(h + (size_t)c0.x * Ff + lane * 2));
        float w0 = __int_as_float(c0.y);
        a0.x = fmaf(w0, v0.x, a0.x); a0.y = fmaf(w0, v0.y, a0.y);
    }
    a0.x += a1.x + a2.x + a3.x;
    a0.y += a1.y + a2.y + a3.y;
    *(__half2*)(g_agg16 + (size_t)w * Ff + lane * 2) = __floats2half2_rn(a0.x, a0.y);
}

// ---------------------------------------------------------------------------
// GEMM h0 = relu(x @ W0^T + b).  Also writes fp16 shadow for the gather.
// ---------------------------------------------------------------------------
__global__ void __launch_bounds__(256)
gemm_h0_kernel(const float* __restrict__ x, const float* __restrict__ w0,
               const float* __restrict__ b) {
    __shared__ __align__(16) float As[64][128];  // [k][node]
    __shared__ __align__(16) float Ws[64][64];   // [k][f]
    int t = threadIdx.x;
    int n0 = blockIdx.x * 128;

    for (int i = t; i < 4096; i += 256) {
        int k = i >> 6, f = i & 63;
        Ws[k][f] = w0[f * 64 + k];  // transpose: need W0[f][k] at [k][f]
    }
    for (int i = t * 4; i < 8192; i += 1024) {
        int node = i >> 6, k = i & 63;
        int gn = n0 + node;
        float4 v = make_float4(0.f, 0.f, 0.f, 0.f);
        if (gn < Nn) v = *(const float4*)(x + (size_t)gn * 64 + k);
        As[k + 0][node] = v.x; As[k + 1][node] = v.y;
        As[k + 2][node] = v.z; As[k + 3][node] = v.w;
    }
    __syncthreads();

    int tf = (t & 15) * 4;
    int tn = (t >> 4) * 8;
    float acc[8][4];
#pragma unroll
    for (int j = 0; j < 8; j++)
        acc[j][0] = acc[j][1] = acc[j][2] = acc[j][3] = 0.f;

#pragma unroll 8
    for (int k = 0; k < 64; k++) {
        float4 w4 = *(const float4*)&Ws[k][tf];
        float4 b0v = *(const float4*)&As[k][tn];
        float4 b1v = *(const float4*)&As[k][tn + 4];
        float a[8] = {b0v.x, b0v.y, b0v.z, b0v.w, b1v.x, b1v.y, b1v.z, b1v.w};
#pragma unroll
        for (int j = 0; j < 8; j++) {
            acc[j][0] = fmaf(a[j], w4.x, acc[j][0]);
            acc[j][1] = fmaf(a[j], w4.y, acc[j][1]);
            acc[j][2] = fmaf(a[j], w4.z, acc[j][2]);
            acc[j][3] = fmaf(a[j], w4.w, acc[j][3]);
        }
    }
    float4 bv = *(const float4*)(b + tf);
#pragma unroll
    for (int j = 0; j < 8; j++) {
        int gn = n0 + tn + j;
        if (gn < Nn) {
            float4 r;
            r.x = fmaxf(acc[j][0] + bv.x, 0.f);
            r.y = fmaxf(acc[j][1] + bv.y, 0.f);
            r.z = fmaxf(acc[j][2] + bv.z, 0.f);
            r.w = fmaxf(acc[j][3] + bv.w, 0.f);
            *(float4*)&g_h0[(size_t)gn * 64 + tf] = r;
            __half2 p0 = __floats2half2_rn(r.x, r.y);
            __half2 p1 = __floats2half2_rn(r.z, r.w);
            *(__half2*)&g_h16[(size_t)gn * 64 + tf] = p0;
            *(__half2*)&g_h16[(size_t)gn * 64 + tf + 2] = p1;
        }
    }
}

// ---------------------------------------------------------------------------
// Fused conv GEMM (packed f32x2 FFMA2 main loop):
//   out = prev + relu( (0.1*agg16 + 0.9*h0) @ W1 )
// layer 0: prev = h0,   out = g_out1 (+ fp16 shadow g_o16)
// layer 1: prev = out1, out = d_out
// ---------------------------------------------------------------------------
__global__ void __launch_bounds__(256)
gemm_conv_kernel(const float* __restrict__ w1, int layer,
                 float* __restrict__ dout) {
    __shared__ __align__(16) float As[64][128];
    __shared__ __align__(16) float Ws[64][64];
    int t = threadIdx.x;
    int n0 = blockIdx.x * 128;
    const float* __restrict__ prev = layer ? g_out1 : g_h0;
    float* __restrict__ out = layer ? dout : g_out1;

    for (int i = t; i < 4096; i += 256) {
        Ws[i >> 6][i & 63] = w1[i];  // already [k][f]
    }
    for (int i = t * 4; i < 8192; i += 1024) {
        int node = i >> 6, k = i & 63;
        int gn = n0 + node;
        float4 v = make_float4(0.f, 0.f, 0.f, 0.f);
        if (gn < Nn) {
            float2 alo = __half22float2(*(const __half2*)(g_agg16 + (size_t)gn * 64 + k));
            float2 ahi = __half22float2(*(const __half2*)(g_agg16 + (size_t)gn * 64 + k + 2));
            float4 h = *(const float4*)(g_h0 + (size_t)gn * 64 + k);
            v.x = fmaf(0.1f, alo.x, 0.9f * h.x);
            v.y = fmaf(0.1f, alo.y, 0.9f * h.y);
            v.z = fmaf(0.1f, ahi.x, 0.9f * h.z);
            v.w = fmaf(0.1f, ahi.y, 0.9f * h.w);
        }
        As[k + 0][node] = v.x; As[k + 1][node] = v.y;
        As[k + 2][node] = v.z; As[k + 3][node] = v.w;
    }
    __syncthreads();

    int tf = (t & 15) * 4;
    int tn = (t >> 4) * 8;

    ull acc2[4][4];
#pragma unroll
    for (int jp = 0; jp < 4; jp++)
#pragma unroll
        for (int c = 0; c < 4; c++) acc2[jp][c] = 0ull;

#pragma unroll 8
    for (int k = 0; k < 64; k++) {
        float4 w4 = *(const float4*)&Ws[k][tf];
        ull wd0 = dup2(w4.x), wd1 = dup2(w4.y), wd2 = dup2(w4.z), wd3 = dup2(w4.w);
        ulonglong2 ap0 = *(const ulonglong2*)&As[k][tn];
        ulonglong2 ap1 = *(const ulonglong2*)&As[k][tn + 4];
        ull ap[4] = {ap0.x, ap0.y, ap1.x, ap1.y};
#pragma unroll
        for (int jp = 0; jp < 4; jp++) {
            acc2[jp][0] = fma2(ap[jp], wd0, acc2[jp][0]);
            acc2[jp][1] = fma2(ap[jp], wd1, acc2[jp][1]);
            acc2[jp][2] = fma2(ap[jp], wd2, acc2[jp][2]);
            acc2[jp][3] = fma2(ap[jp], wd3, acc2[jp][3]);
        }
    }

    float acc[8][4];
#pragma unroll
    for (int jp = 0; jp < 4; jp++)
#pragma unroll
        for (int c = 0; c < 4; c++)
            unpack2(acc2[jp][c], acc[2 * jp][c], acc[2 * jp + 1][c]);

#pragma unroll
    for (int j = 0; j < 8; j++) {
        int gn = n0 + tn + j;
        if (gn < Nn) {
            float4 p = *(const float4*)(prev + (size_t)gn * 64 + tf);
            float4 r;
            r.x = p.x + fmaxf(acc[j][0], 0.f);
            r.y = p.y + fmaxf(acc[j][1], 0.f);
            r.z = p.z + fmaxf(acc[j][2], 0.f);
            r.w = p.w + fmaxf(acc[j][3], 0.f);
            *(float4*)(out + (size_t)gn * 64 + tf) = r;
            if (layer == 0) {
                __half2 p0 = __floats2half2_rn(r.x, r.y);
                __half2 p1 = __floats2half2_rn(r.z, r.w);
                *(__half2*)&g_o16[(size_t)gn * 64 + tf] = p0;
                *(__half2*)&g_o16[(size_t)gn * 64 + tf + 2] = p1;
            }
        }
    }
}

// ---------------------------------------------------------------------------
extern "C" void kernel_launch(void* const* d_in, const int* in_sizes, int n_in,
                              void* d_out, int out_size) {
    const float* x  = (const float*)d_in[0];
    const int*   ei = (const int*)d_in[1];   // int32 (harness: int64 -> int32)
    const float* ew = (const float*)d_in[2];
    // d_in[3] = edge_attr (unused by the module)
    const float* w0 = (const float*)d_in[4];
    const float* b0 = (const float*)d_in[5];
    const float* w1 = (const float*)d_in[6];
    float* out = (float*)d_out;

    const int* rows = ei;
    const int* cols = ei + Ee;

    const int E2B = (Ee / 2 + 255) / 256;   // 2 edges per thread
    const int NB = (Nn + 255) / 256;
    const int GB = (Nn + 127) / 128;
    const int WB = (Nn + 7) / 8;

    static cudaStream_t s1 = nullptr;
    static cudaEvent_t ev_fork = nullptr, ev_join = nullptr;
    if (s1 == nullptr) {
        cudaStreamCreateWithFlags(&s1, cudaStreamNonBlocking);
        cudaEventCreateWithFlags(&ev_fork, cudaEventDisableTiming);
        cudaEventCreateWithFlags(&ev_join, cudaEventDisableTiming);
    }

    // Fork: gemm_h0 is independent of the CSR build chain.
    cudaEventRecord(ev_fork, 0);
    cudaStreamWaitEvent(s1, ev_fork, 0);
    gemm_h0_kernel<<<GB, 256, 0, s1>>>(x, w0, b0);
    cudaEventRecord(ev_join, s1);

    // CSR build chain on the main stream.
    zero_kernel<<<NB, 256>>>();
    deg_kernel<<<E2B, 256>>>(cols, ew);       // 1 packed atomic per edge
    alloc_kernel<<<NB, 256>>>();              // scan + dinv in one kernel
    scatter_kernel<<<E2B, 256>>>(rows, cols, ew);

    // Join: gather needs both h16 and the CSR.
    cudaStreamWaitEvent(0, ev_join, 0);

    // layer 1
    gather_kernel<<<WB, 256>>>(0);
    gemm_conv_kernel<<<GB, 256>>>(w1, 0, out);

    // layer 2
    gather_kernel<<<WB, 256>>>(1);
    gemm_conv_kernel<<<GB, 256>>>(w1 + 64 * 64, 1, out);
}